// round 14
// baseline (speedup 1.0000x reference)
#include <cuda_runtime.h>
#include <cfloat>

// R14 = R13 (exact predicate-free kernel, reproducibly 35.4-35.65us / 6.0TB/s)
// with EVICT-FIRST LOADS (__ldcs) on the one-touch x stream. w/b loads stay
// default-cached (L1/L2-hot across all 8192 blocks). Last cell of the
// load/store cache-policy matrix on the winning chassis.
//
// Math: 101 x (relu o affine), w > 0, collapses exactly to
//   f(x) = S * max(x, C) + O,  composed associatively per-warp via shuffles:
//   (g o f): S = Sg*Sf,  C = max(Cf, (Cg - Of)/Sf),  O = Sg*Of + Og.

__device__ __forceinline__ void warp_scan_coeffs(const float* __restrict__ w,
                                                 const float* __restrict__ b,
                                                 int n_layers, int lane,
                                                 float& S, float& C, float& O) {
    S = 1.0f; C = -FLT_MAX; O = 0.0f;
    #pragma unroll
    for (int k = 0; k < 4; ++k) {
        const int idx = 4 * lane + k;             // independent loads
        if (idx < n_layers) {
            const float wi = w[idx];
            const float bi = b[idx];
            const float Cl = __fdividef(-bi, wi);
            C = fmaxf(C, __fdividef(Cl - O, S));
            S = wi * S;
            O = fmaf(wi, O, bi);
        }
    }
    #pragma unroll
    for (int d = 1; d < 32; d <<= 1) {
        const float Sp = __shfl_up_sync(0xffffffffu, S, d);
        const float Cp = __shfl_up_sync(0xffffffffu, C, d);
        const float Op = __shfl_up_sync(0xffffffffu, O, d);
        if (lane >= d) {
            C = fmaxf(Cp, __fdividef(C - Op, Sp));
            O = fmaf(S, Op, O);   // uses pre-update S
            S = S * Sp;
        }
    }
    S = __shfl_sync(0xffffffffu, S, 31);
    C = __shfl_sync(0xffffffffu, C, 31);
    O = __shfl_sync(0xffffffffu, O, 31);
}

// Exact path: n4 % 1024 == 0 — no predicates, no tail, evict-first loads.
__global__ __launch_bounds__(256)
void fused_flat4_exact_ldcs_kernel(const float4* __restrict__ x4,
                                   float4* __restrict__ o4,
                                   const float* __restrict__ w,
                                   const float* __restrict__ b,
                                   int n_layers) {
    const int tid  = threadIdx.x;
    const int lane = tid & 31;
    const int base = blockIdx.x * 1024 + tid;

    // Prefetch all four elements FIRST (evict-first: one-touch stream).
    const float4 v0 = __ldcs(x4 + base);
    const float4 v1 = __ldcs(x4 + base + 256);
    const float4 v2 = __ldcs(x4 + base + 512);
    const float4 v3 = __ldcs(x4 + base + 768);

    float S, C, O;
    warp_scan_coeffs(w, b, n_layers, lane, S, C, O);

    float4 r;
    r.x = fmaf(S, fmaxf(v0.x, C), O); r.y = fmaf(S, fmaxf(v0.y, C), O);
    r.z = fmaf(S, fmaxf(v0.z, C), O); r.w = fmaf(S, fmaxf(v0.w, C), O);
    o4[base] = r;
    r.x = fmaf(S, fmaxf(v1.x, C), O); r.y = fmaf(S, fmaxf(v1.y, C), O);
    r.z = fmaf(S, fmaxf(v1.z, C), O); r.w = fmaf(S, fmaxf(v1.w, C), O);
    o4[base + 256] = r;
    r.x = fmaf(S, fmaxf(v2.x, C), O); r.y = fmaf(S, fmaxf(v2.y, C), O);
    r.z = fmaf(S, fmaxf(v2.z, C), O); r.w = fmaf(S, fmaxf(v2.w, C), O);
    o4[base + 512] = r;
    r.x = fmaf(S, fmaxf(v3.x, C), O); r.y = fmaf(S, fmaxf(v3.y, C), O);
    r.z = fmaf(S, fmaxf(v3.z, C), O); r.w = fmaf(S, fmaxf(v3.w, C), O);
    o4[base + 768] = r;
}

// Guarded fallback (identical to the validated R7/R12 kernel).
__global__ __launch_bounds__(256)
void fused_flat4_ws_kernel(const float4* __restrict__ x4,
                           float4* __restrict__ o4,
                           const float* __restrict__ w,
                           const float* __restrict__ b,
                           int n_layers, int n4, int n,
                           const float* __restrict__ x,
                           float* __restrict__ out) {
    const int tid  = threadIdx.x;
    const int lane = tid & 31;
    const int base = blockIdx.x * 1024 + tid;

    float4 v0, v1, v2, v3;
    const bool ok0 = (base       < n4);
    const bool ok1 = (base + 256 < n4);
    const bool ok2 = (base + 512 < n4);
    const bool ok3 = (base + 768 < n4);
    if (ok0) v0 = x4[base];
    if (ok1) v1 = x4[base + 256];
    if (ok2) v2 = x4[base + 512];
    if (ok3) v3 = x4[base + 768];

    float S, C, O;
    warp_scan_coeffs(w, b, n_layers, lane, S, C, O);

    float4 r;
    if (ok0) {
        r.x = fmaf(S, fmaxf(v0.x, C), O); r.y = fmaf(S, fmaxf(v0.y, C), O);
        r.z = fmaf(S, fmaxf(v0.z, C), O); r.w = fmaf(S, fmaxf(v0.w, C), O);
        o4[base] = r;
    }
    if (ok1) {
        r.x = fmaf(S, fmaxf(v1.x, C), O); r.y = fmaf(S, fmaxf(v1.y, C), O);
        r.z = fmaf(S, fmaxf(v1.z, C), O); r.w = fmaf(S, fmaxf(v1.w, C), O);
        o4[base + 256] = r;
    }
    if (ok2) {
        r.x = fmaf(S, fmaxf(v2.x, C), O); r.y = fmaf(S, fmaxf(v2.y, C), O);
        r.z = fmaf(S, fmaxf(v2.z, C), O); r.w = fmaf(S, fmaxf(v2.w, C), O);
        o4[base + 512] = r;
    }
    if (ok3) {
        r.x = fmaf(S, fmaxf(v3.x, C), O); r.y = fmaf(S, fmaxf(v3.y, C), O);
        r.z = fmaf(S, fmaxf(v3.z, C), O); r.w = fmaf(S, fmaxf(v3.w, C), O);
        o4[base + 768] = r;
    }

    if (blockIdx.x == 0 && tid == 0) {
        for (int j = n4 * 4; j < n; ++j) {
            out[j] = fmaf(S, fmaxf(x[j], C), O);
        }
    }
}

extern "C" void kernel_launch(void* const* d_in, const int* in_sizes, int n_in,
                              void* d_out, int out_size) {
    const float* x = (const float*)d_in[0];
    const float* w = (const float*)d_in[1];
    const float* b = (const float*)d_in[2];
    float* out = (float*)d_out;

    const int n        = in_sizes[0];
    const int n_layers = in_sizes[1];
    const int n4       = n / 4;

    const int threads = 256;

    if ((n % 4) == 0 && (n4 % 1024) == 0) {
        const int blocks = n4 / 1024;
        fused_flat4_exact_ldcs_kernel<<<blocks, threads>>>(
            (const float4*)x, (float4*)out, w, b, n_layers);
    } else {
        const int blocks = (n4 + 1023) / 1024;
        fused_flat4_ws_kernel<<<blocks, threads>>>(
            (const float4*)x, (float4*)out, w, b, n_layers, n4, n, x, out);
    }
}

// round 15
// speedup vs baseline: 1.0368x; 1.0368x over previous
#include <cuda_runtime.h>
#include <cfloat>

// ============================ FINAL BUILD ============================
// 101 x (relu o scalar-affine), w > 0, collapses EXACTLY to
//     f(x) = S * max(x, C) + O
// because a clamp-below composed with a positive affine remains a single
// clamp-below. Prefix triples compose associatively:
//     (g o f): S = Sg*Sf,  C = max(Cf, (Cg - Of)/Sf),  O = Sg*Of + Og.
//
// Kernel structure (winner across 14 measured rounds):
//   * flat grid, 4 float4 per thread, contiguous 1024-float4 block tiles
//   * all 4 LDG.128 prefetched first (~577cyc DRAM latency in flight)
//   * EVERY warp redundantly computes the 101-layer scan via shuffles in
//     the shadow of its own loads — no __syncthreads, no shared memory
//   * exact (predicate-free) kernel when n4 % 1024 == 0; guarded fallback
//
// Convergence evidence: tile 2/4/8, barrier vs per-warp scan, divide vs
// division-free scan, __stcs/__ldcs, v8 256-bit ld/st, predicate removal —
// all pin at 35.4-35.9us kernel @ 5.9-6.0 TB/s (~75% of 8TB/s spec), the
// chip's fp32 one-touch r+w stream ceiling. Traffic (128 MiB in + 128 MiB
// out) is algorithmically irreducible.
// =====================================================================

__device__ __forceinline__ void warp_scan_coeffs(const float* __restrict__ w,
                                                 const float* __restrict__ b,
                                                 int n_layers, int lane,
                                                 float& S, float& C, float& O) {
    S = 1.0f; C = -FLT_MAX; O = 0.0f;
    #pragma unroll
    for (int k = 0; k < 4; ++k) {
        const int idx = 4 * lane + k;             // independent loads
        if (idx < n_layers) {
            const float wi = w[idx];
            const float bi = b[idx];
            const float Cl = __fdividef(-bi, wi);
            C = fmaxf(C, __fdividef(Cl - O, S));
            S = wi * S;
            O = fmaf(wi, O, bi);
        }
    }
    #pragma unroll
    for (int d = 1; d < 32; d <<= 1) {
        const float Sp = __shfl_up_sync(0xffffffffu, S, d);
        const float Cp = __shfl_up_sync(0xffffffffu, C, d);
        const float Op = __shfl_up_sync(0xffffffffu, O, d);
        if (lane >= d) {
            C = fmaxf(Cp, __fdividef(C - Op, Sp));
            O = fmaf(S, Op, O);   // uses pre-update S
            S = S * Sp;
        }
    }
    S = __shfl_sync(0xffffffffu, S, 31);
    C = __shfl_sync(0xffffffffu, C, 31);
    O = __shfl_sync(0xffffffffu, O, 31);
}

// Exact path: n4 % 1024 == 0 — no predicates, no tail.
__global__ __launch_bounds__(256)
void fused_flat4_exact_kernel(const float4* __restrict__ x4,
                              float4* __restrict__ o4,
                              const float* __restrict__ w,
                              const float* __restrict__ b,
                              int n_layers) {
    const int tid  = threadIdx.x;
    const int lane = tid & 31;
    const int base = blockIdx.x * 1024 + tid;

    // Prefetch all four elements FIRST: DRAM latency overlaps the scan.
    const float4 v0 = x4[base];
    const float4 v1 = x4[base + 256];
    const float4 v2 = x4[base + 512];
    const float4 v3 = x4[base + 768];

    float S, C, O;
    warp_scan_coeffs(w, b, n_layers, lane, S, C, O);

    float4 r;
    r.x = fmaf(S, fmaxf(v0.x, C), O); r.y = fmaf(S, fmaxf(v0.y, C), O);
    r.z = fmaf(S, fmaxf(v0.z, C), O); r.w = fmaf(S, fmaxf(v0.w, C), O);
    o4[base] = r;
    r.x = fmaf(S, fmaxf(v1.x, C), O); r.y = fmaf(S, fmaxf(v1.y, C), O);
    r.z = fmaf(S, fmaxf(v1.z, C), O); r.w = fmaf(S, fmaxf(v1.w, C), O);
    o4[base + 256] = r;
    r.x = fmaf(S, fmaxf(v2.x, C), O); r.y = fmaf(S, fmaxf(v2.y, C), O);
    r.z = fmaf(S, fmaxf(v2.z, C), O); r.w = fmaf(S, fmaxf(v2.w, C), O);
    o4[base + 512] = r;
    r.x = fmaf(S, fmaxf(v3.x, C), O); r.y = fmaf(S, fmaxf(v3.y, C), O);
    r.z = fmaf(S, fmaxf(v3.z, C), O); r.w = fmaf(S, fmaxf(v3.w, C), O);
    o4[base + 768] = r;
}

// Guarded fallback for arbitrary n (validated R7/R12 kernel).
__global__ __launch_bounds__(256)
void fused_flat4_ws_kernel(const float4* __restrict__ x4,
                           float4* __restrict__ o4,
                           const float* __restrict__ w,
                           const float* __restrict__ b,
                           int n_layers, int n4, int n,
                           const float* __restrict__ x,
                           float* __restrict__ out) {
    const int tid  = threadIdx.x;
    const int lane = tid & 31;
    const int base = blockIdx.x * 1024 + tid;

    float4 v0, v1, v2, v3;
    const bool ok0 = (base       < n4);
    const bool ok1 = (base + 256 < n4);
    const bool ok2 = (base + 512 < n4);
    const bool ok3 = (base + 768 < n4);
    if (ok0) v0 = x4[base];
    if (ok1) v1 = x4[base + 256];
    if (ok2) v2 = x4[base + 512];
    if (ok3) v3 = x4[base + 768];

    float S, C, O;
    warp_scan_coeffs(w, b, n_layers, lane, S, C, O);

    float4 r;
    if (ok0) {
        r.x = fmaf(S, fmaxf(v0.x, C), O); r.y = fmaf(S, fmaxf(v0.y, C), O);
        r.z = fmaf(S, fmaxf(v0.z, C), O); r.w = fmaf(S, fmaxf(v0.w, C), O);
        o4[base] = r;
    }
    if (ok1) {
        r.x = fmaf(S, fmaxf(v1.x, C), O); r.y = fmaf(S, fmaxf(v1.y, C), O);
        r.z = fmaf(S, fmaxf(v1.z, C), O); r.w = fmaf(S, fmaxf(v1.w, C), O);
        o4[base + 256] = r;
    }
    if (ok2) {
        r.x = fmaf(S, fmaxf(v2.x, C), O); r.y = fmaf(S, fmaxf(v2.y, C), O);
        r.z = fmaf(S, fmaxf(v2.z, C), O); r.w = fmaf(S, fmaxf(v2.w, C), O);
        o4[base + 512] = r;
    }
    if (ok3) {
        r.x = fmaf(S, fmaxf(v3.x, C), O); r.y = fmaf(S, fmaxf(v3.y, C), O);
        r.z = fmaf(S, fmaxf(v3.z, C), O); r.w = fmaf(S, fmaxf(v3.w, C), O);
        o4[base + 768] = r;
    }

    if (blockIdx.x == 0 && tid == 0) {
        for (int j = n4 * 4; j < n; ++j) {
            out[j] = fmaf(S, fmaxf(x[j], C), O);
        }
    }
}

extern "C" void kernel_launch(void* const* d_in, const int* in_sizes, int n_in,
                              void* d_out, int out_size) {
    const float* x = (const float*)d_in[0];
    const float* w = (const float*)d_in[1];
    const float* b = (const float*)d_in[2];
    float* out = (float*)d_out;

    const int n        = in_sizes[0];
    const int n_layers = in_sizes[1];
    const int n4       = n / 4;

    const int threads = 256;

    if ((n % 4) == 0 && (n4 % 1024) == 0) {
        const int blocks = n4 / 1024;
        fused_flat4_exact_kernel<<<blocks, threads>>>(
            (const float4*)x, (float4*)out, w, b, n_layers);
    } else {
        const int blocks = (n4 + 1023) / 1024;
        fused_flat4_ws_kernel<<<blocks, threads>>>(
            (const float4*)x, (float4*)out, w, b, n_layers, n4, n, x, out);
    }
}